// round 14
// baseline (speedup 1.0000x reference)
#include <cuda_runtime.h>

// Problem constants (fixed by the reference)
#define NNODES 50000
#define MAXE   1600000
#define ETOTMAX (MAXE + NNODES)
#define HF     128      // H*F
#define FDIM   64
#define NCLS   16
#define SCAN_NBLK 49    // cdiv(NNODES, 1024)
#define NHALF1 25088    // multiple of 128
#define NHALF2 (NNODES - NHALF1)

// ---------------- scratch (device globals; no allocation allowed) -------------
__device__ float    g_h[NNODES * HF];
__device__ float    g_h2[NNODES * HF];
__device__ float    g_as[NNODES * 2];
__device__ float    g_ad[NNODES * 2];
__device__ float    g_z1[NNODES * 512];
// CSR scratch
__device__ int      g_deg[NNODES];
__device__ int      g_pos[NNODES];
__device__ int      g_off[NNODES + 1];
__device__ int      g_csr[ETOTMAX];
__device__ int      g_bsum[64];

static inline int cdiv(int a, int b) { return (a + b - 1) / b; }

// ============================ logits zero-init ================================
__global__ void zero_logits_kernel(float* __restrict__ logits)
{
    int i = blockIdx.x * blockDim.x + threadIdx.x;      // float4 index
    int total = NNODES * NCLS / 4;
    if (i < total)
        reinterpret_cast<float4*>(logits)[i] = make_float4(0.f, 0.f, 0.f, 0.f);
}

// ============================ CSR build ======================================
__global__ void csr_zero_kernel()
{
    int i = blockIdx.x * blockDim.x + threadIdx.x;
    int4 one = make_int4(1, 1, 1, 1);
    if (i * 4 + 3 < NNODES) {
        *reinterpret_cast<int4*>(&g_deg[i * 4]) = one;
        *reinterpret_cast<int4*>(&g_pos[i * 4]) = one;
    } else {
        for (int j = i * 4; j < NNODES; j++) { g_deg[j] = 1; g_pos[j] = 1; }
    }
}

__global__ void csr_count_kernel(const int* __restrict__ ei, int E)
{
    int i = blockIdx.x * blockDim.x + threadIdx.x;
    if (i >= E) return;
    atomicAdd(&g_deg[ei[E + i]], 1);
}

__global__ void csr_scan1_kernel()
{
    __shared__ int buf[1024];
    int t = threadIdx.x;
    int i = blockIdx.x * 1024 + t;
    int v = (i < NNODES) ? g_deg[i] : 0;
    buf[t] = v;
    __syncthreads();
#pragma unroll
    for (int off = 1; off < 1024; off <<= 1) {
        int tv = (t >= off) ? buf[t - off] : 0;
        __syncthreads();
        buf[t] += tv;
        __syncthreads();
    }
    if (i < NNODES) g_off[i + 1] = buf[t];
    if (t == 1023) g_bsum[blockIdx.x] = buf[t];
}

__global__ void csr_scan_fix_kernel()
{
    __shared__ int carry[SCAN_NBLK];
    int t = threadIdx.x;
    if (t < SCAN_NBLK) carry[t] = g_bsum[t];
    __syncthreads();
    if (t == 0) {
        int run = 0;
#pragma unroll
        for (int b = 0; b < SCAN_NBLK; b++) { int v = carry[b]; carry[b] = run; run += v; }
    }
    __syncthreads();
    int i = blockIdx.x * blockDim.x + t;
    if (i == 0) { g_off[0] = 0; g_csr[0] = 0; }
    if (i < NNODES) {
        int v = g_off[i + 1] + carry[i >> 10];
        g_off[i + 1] = v;
        if (i + 1 < NNODES) g_csr[v] = i + 1;
    }
}

__global__ void csr_scatter_kernel(const int* __restrict__ ei, int E)
{
    int i = blockIdx.x * blockDim.x + threadIdx.x;
    if (i >= E) return;
    int s = ei[i], d = ei[E + i];
    int idx = g_off[d] + atomicAdd(&g_pos[d], 1);
    g_csr[idx] = s;
}

// ============================ tf32 helpers ===================================
__device__ __forceinline__ unsigned f2tf32(float f)
{
    unsigned r;
    asm("cvt.rna.tf32.f32 %0, %1;" : "=r"(r) : "f"(f));
    return r;
}

__device__ __forceinline__ void mma_tf32(float c[4], const unsigned a[4],
                                         unsigned b0, unsigned b1)
{
    asm volatile(
        "mma.sync.aligned.m16n8k8.row.col.f32.tf32.tf32.f32 "
        "{%0,%1,%2,%3},{%4,%5,%6,%7},{%8,%9},{%0,%1,%2,%3};"
        : "+f"(c[0]), "+f"(c[1]), "+f"(c[2]), "+f"(c[3])
        : "r"(a[0]), "r"(a[1]), "r"(a[2]), "r"(a[3]), "r"(b0), "r"(b1));
}

// ============================ pipelined tf32 GEMM ============================
// A/C pointers pre-offset to the row range; rowBase = global row of local row 0
// (used only by the fused alpha writes).
// If lw3fused != nullptr (MLP2): C may be nullptr (z2 never materialized);
// the epilogue computes this block's 128x16 logits contribution:
// relu(acc+bias) @ lw3[col0:col0+128, :] and atomically accumulates into
// logitsOut (pre-offset per half). Exactly 2 smem contributions per cell and
// 2 global contributions per logit -> bitwise deterministic.
__global__ __launch_bounds__(256) void gemm_tf32_kernel(
    const float* __restrict__ A, const float* __restrict__ B,
    const float* __restrict__ bias, float* __restrict__ C,
    const float* __restrict__ alpha_src, const float* __restrict__ alpha_dst,
    const float* __restrict__ lw3fused, float* __restrict__ logitsOut,
    int rowBase, int M, int Nn, int K, int doRelu)
{
    __shared__ float As[2][16][132];
    __shared__ float Bs[2][16][132];

    int tid = threadIdx.x;
    int lane = tid & 31, wid = tid >> 5;
    int wr = wid >> 1, wc = wid & 1;
    int row0 = blockIdx.y * 128, col0 = blockIdx.x * 128;
    int g = lane >> 2, tig = lane & 3;

    float acc[2][8][4];
#pragma unroll
    for (int mi = 0; mi < 2; mi++)
#pragma unroll
        for (int ni = 0; ni < 8; ni++)
#pragma unroll
            for (int q = 0; q < 4; q++) acc[mi][ni][q] = 0.f;

    int ar = tid >> 2;
    int akc = (tid & 3) * 4;
    int bkr = tid >> 5;
    int bnc = (tid & 31) * 4;

    float4 ra[2], rb[2];

    auto load_tiles = [&](int k0) {
#pragma unroll
        for (int rr = 0; rr < 2; rr++) {
            int grow = row0 + ar + rr * 64;
            ra[rr] = make_float4(0.f, 0.f, 0.f, 0.f);
            if (grow < M)
                ra[rr] = *reinterpret_cast<const float4*>(&A[(long)grow * K + k0 + akc]);
        }
#pragma unroll
        for (int rr = 0; rr < 2; rr++) {
            int kr = k0 + bkr + rr * 8;
            rb[rr] = *reinterpret_cast<const float4*>(&B[(long)kr * Nn + col0 + bnc]);
        }
    };

    auto store_tiles = [&](int buf) {
#pragma unroll
        for (int rr = 0; rr < 2; rr++) {
            As[buf][akc + 0][ar + rr * 64] = __uint_as_float(f2tf32(ra[rr].x));
            As[buf][akc + 1][ar + rr * 64] = __uint_as_float(f2tf32(ra[rr].y));
            As[buf][akc + 2][ar + rr * 64] = __uint_as_float(f2tf32(ra[rr].z));
            As[buf][akc + 3][ar + rr * 64] = __uint_as_float(f2tf32(ra[rr].w));
        }
#pragma unroll
        for (int rr = 0; rr < 2; rr++) {
            float4 t;
            t.x = __uint_as_float(f2tf32(rb[rr].x));
            t.y = __uint_as_float(f2tf32(rb[rr].y));
            t.z = __uint_as_float(f2tf32(rb[rr].z));
            t.w = __uint_as_float(f2tf32(rb[rr].w));
            *reinterpret_cast<float4*>(&Bs[buf][bkr + rr * 8][bnc]) = t;
        }
    };

    int nk = K >> 4;
    load_tiles(0);
    store_tiles(0);
    __syncthreads();

    for (int it = 0; it < nk; it++) {
        int cur = it & 1;
        bool has_next = (it + 1 < nk);
        if (has_next) load_tiles((it + 1) << 4);

#pragma unroll
        for (int ks = 0; ks < 16; ks += 8) {
            unsigned af[2][4];
#pragma unroll
            for (int mi = 0; mi < 2; mi++) {
                int mb = wr * 32 + mi * 16 + g;
                af[mi][0] = __float_as_uint(As[cur][ks + tig][mb]);
                af[mi][1] = __float_as_uint(As[cur][ks + tig][mb + 8]);
                af[mi][2] = __float_as_uint(As[cur][ks + tig + 4][mb]);
                af[mi][3] = __float_as_uint(As[cur][ks + tig + 4][mb + 8]);
            }
#pragma unroll
            for (int ni = 0; ni < 8; ni++) {
                int nb = wc * 64 + ni * 8 + g;
                unsigned b0 = __float_as_uint(Bs[cur][ks + tig][nb]);
                unsigned b1 = __float_as_uint(Bs[cur][ks + tig + 4][nb]);
                mma_tf32(acc[0][ni], af[0], b0, b1);
                mma_tf32(acc[1][ni], af[1], b0, b1);
            }
        }

        if (has_next) store_tiles(cur ^ 1);
        __syncthreads();
    }

    // standard epilogue: store C (+bias)(+relu), skipped when C == nullptr
    if (C) {
#pragma unroll
        for (int mi = 0; mi < 2; mi++) {
#pragma unroll
            for (int ni = 0; ni < 8; ni++) {
                int r0 = row0 + wr * 32 + mi * 16 + g;
                int c0 = col0 + wc * 64 + ni * 8 + 2 * tig;
#pragma unroll
                for (int half = 0; half < 2; half++) {
                    int gr = r0 + half * 8;
                    if (gr >= M) continue;
                    float v0 = acc[mi][ni][half * 2 + 0];
                    float v1 = acc[mi][ni][half * 2 + 1];
                    if (bias) { v0 += bias[c0]; v1 += bias[c0 + 1]; }
                    if (doRelu) { v0 = fmaxf(v0, 0.f); v1 = fmaxf(v1, 0.f); }
                    C[(long)gr * Nn + c0] = v0;
                    C[(long)gr * Nn + c0 + 1] = v1;
                }
            }
        }
    }

    // fused alpha epilogue (GAT layers only)
    if (alpha_src) {
        float cs[8][2], cd[8][2];
#pragma unroll
        for (int ni = 0; ni < 8; ni++) {
            int c = wc * 64 + ni * 8 + 2 * tig;
            cs[ni][0] = alpha_src[c];     cs[ni][1] = alpha_src[c + 1];
            cd[ni][0] = alpha_dst[c];     cd[ni][1] = alpha_dst[c + 1];
        }
#pragma unroll
        for (int mi = 0; mi < 2; mi++) {
#pragma unroll
            for (int half = 0; half < 2; half++) {
                float ps = 0.f, pd = 0.f;
#pragma unroll
                for (int ni = 0; ni < 8; ni++) {
                    float v0 = acc[mi][ni][half * 2 + 0];
                    float v1 = acc[mi][ni][half * 2 + 1];
                    ps = fmaf(v0, cs[ni][0], fmaf(v1, cs[ni][1], ps));
                    pd = fmaf(v0, cd[ni][0], fmaf(v1, cd[ni][1], pd));
                }
                ps += __shfl_down_sync(0xffffffffu, ps, 1, 4);
                ps += __shfl_down_sync(0xffffffffu, ps, 2, 4);
                pd += __shfl_down_sync(0xffffffffu, pd, 1, 4);
                pd += __shfl_down_sync(0xffffffffu, pd, 2, 4);
                int gr = row0 + wr * 32 + mi * 16 + g + half * 8;
                if (tig == 0 && gr < M) {
                    g_as[(rowBase + gr) * 2 + wc] = ps;
                    g_ad[(rowBase + gr) * 2 + wc] = pd;
                }
            }
        }
    }

    // fused logits epilogue (MLP2 only)
    if (lw3fused) {
        float* smL   = &As[0][0][0];     // 2048 floats: lw3 slice [128 cols][16]
        float* smAcc = &Bs[0][0][0];     // 2048 floats: block logits accum [128 rows][16]
        // load lw3 slice (rows col0..col0+127, contiguous) + zero accumulator
        {
            int base = tid * 8;
            const float4* src = reinterpret_cast<const float4*>(&lw3fused[(long)col0 * 16 + base]);
            float4* d0 = reinterpret_cast<float4*>(&smL[base]);
            d0[0] = src[0];
            d0[1] = src[1];
            float4* z = reinterpret_cast<float4*>(&smAcc[base]);
            z[0] = make_float4(0.f, 0.f, 0.f, 0.f);
            z[1] = make_float4(0.f, 0.f, 0.f, 0.f);
        }
        __syncthreads();

#pragma unroll
        for (int mi = 0; mi < 2; mi++) {
#pragma unroll
            for (int half = 0; half < 2; half++) {
                int r_loc = wr * 32 + mi * 16 + g + half * 8;
                int gr = row0 + r_loc;
                float4 part[4];
#pragma unroll
                for (int q = 0; q < 4; q++) part[q] = make_float4(0.f, 0.f, 0.f, 0.f);
#pragma unroll
                for (int ni = 0; ni < 8; ni++) {
                    int c0l = wc * 64 + ni * 8 + 2 * tig;   // local col in [0,128)
                    float v0 = acc[mi][ni][half * 2 + 0] + bias[col0 + c0l];
                    float v1 = acc[mi][ni][half * 2 + 1] + bias[col0 + c0l + 1];
                    v0 = fmaxf(v0, 0.f);
                    v1 = fmaxf(v1, 0.f);
                    const float4* pr0 = reinterpret_cast<const float4*>(&smL[c0l * 16]);
                    const float4* pr1 = reinterpret_cast<const float4*>(&smL[(c0l + 1) * 16]);
#pragma unroll
                    for (int q = 0; q < 4; q++) {
                        float4 a = pr0[q], b = pr1[q];
                        part[q].x = fmaf(v0, a.x, fmaf(v1, b.x, part[q].x));
                        part[q].y = fmaf(v0, a.y, fmaf(v1, b.y, part[q].y));
                        part[q].z = fmaf(v0, a.z, fmaf(v1, b.z, part[q].z));
                        part[q].w = fmaf(v0, a.w, fmaf(v1, b.w, part[q].w));
                    }
                }
                // reduce across the 4 lanes (tig) sharing this row
#pragma unroll
                for (int q = 0; q < 4; q++) {
                    part[q].x += __shfl_down_sync(0xffffffffu, part[q].x, 1, 4);
                    part[q].x += __shfl_down_sync(0xffffffffu, part[q].x, 2, 4);
                    part[q].y += __shfl_down_sync(0xffffffffu, part[q].y, 1, 4);
                    part[q].y += __shfl_down_sync(0xffffffffu, part[q].y, 2, 4);
                    part[q].z += __shfl_down_sync(0xffffffffu, part[q].z, 1, 4);
                    part[q].z += __shfl_down_sync(0xffffffffu, part[q].z, 2, 4);
                    part[q].w += __shfl_down_sync(0xffffffffu, part[q].w, 1, 4);
                    part[q].w += __shfl_down_sync(0xffffffffu, part[q].w, 2, 4);
                }
                if (tig == 0 && gr < M) {
#pragma unroll
                    for (int q = 0; q < 4; q++) {
                        atomicAdd(&smAcc[r_loc * 16 + q * 4 + 0], part[q].x);
                        atomicAdd(&smAcc[r_loc * 16 + q * 4 + 1], part[q].y);
                        atomicAdd(&smAcc[r_loc * 16 + q * 4 + 2], part[q].z);
                        atomicAdd(&smAcc[r_loc * 16 + q * 4 + 3], part[q].w);
                    }
                }
            }
        }
        __syncthreads();
        // flush: each thread handles 8 consecutive values
        {
            int lin = tid * 8;
#pragma unroll
            for (int j = 0; j < 8; j++) {
                int r_loc = (lin + j) >> 4;
                if (row0 + r_loc < M)
                    atomicAdd(&logitsOut[(long)row0 * 16 + lin + j], smAcc[lin + j]);
            }
        }
    }
}

// ---------------- fused softmax + aggregation over node range [n0, n1) -------
__global__ void agg_kernel(const float* __restrict__ bias, float* __restrict__ dst,
                           int n0, int n1)
{
    int n = n0 + ((blockIdx.x * blockDim.x + threadIdx.x) >> 5);
    int lane = threadIdx.x & 31;
    if (n >= n1) return;
    int beg = g_off[n], end = g_off[n + 1];
    float ad0 = g_ad[n * 2 + 0], ad1 = g_ad[n * 2 + 1];
    int head1 = lane >= 16;

    float4 acc = make_float4(0.f, 0.f, 0.f, 0.f);
    float s0 = 0.f, s1 = 0.f;

    for (int base = beg; base < end; base += 32) {
        int cnt = min(32, end - base);
        int sl = 0; float ex0 = 0.f, ex1 = 0.f;
        if (lane < cnt) {
            sl = g_csr[base + lane];
            float2 a = *reinterpret_cast<const float2*>(&g_as[sl * 2]);
            float e0 = a.x + ad0; e0 = fmaxf(e0, 0.2f * e0);
            float e1 = a.y + ad1; e1 = fmaxf(e1, 0.2f * e1);
            ex0 = __expf(e0);
            ex1 = __expf(e1);
        }
        int t = 0;
        for (; t + 4 <= cnt; t += 4) {
            int   sA = __shfl_sync(0xffffffffu, sl, t + 0);
            int   sB = __shfl_sync(0xffffffffu, sl, t + 1);
            int   sC = __shfl_sync(0xffffffffu, sl, t + 2);
            int   sD = __shfl_sync(0xffffffffu, sl, t + 3);
            float wA0 = __shfl_sync(0xffffffffu, ex0, t + 0);
            float wB0 = __shfl_sync(0xffffffffu, ex0, t + 1);
            float wC0 = __shfl_sync(0xffffffffu, ex0, t + 2);
            float wD0 = __shfl_sync(0xffffffffu, ex0, t + 3);
            float wA1 = __shfl_sync(0xffffffffu, ex1, t + 0);
            float wB1 = __shfl_sync(0xffffffffu, ex1, t + 1);
            float wC1 = __shfl_sync(0xffffffffu, ex1, t + 2);
            float wD1 = __shfl_sync(0xffffffffu, ex1, t + 3);
            float4 hA = reinterpret_cast<const float4*>(&g_h[(long)sA * HF])[lane];
            float4 hB = reinterpret_cast<const float4*>(&g_h[(long)sB * HF])[lane];
            float4 hC = reinterpret_cast<const float4*>(&g_h[(long)sC * HF])[lane];
            float4 hD = reinterpret_cast<const float4*>(&g_h[(long)sD * HF])[lane];
            s0 += wA0 + wB0 + wC0 + wD0;
            s1 += wA1 + wB1 + wC1 + wD1;
            float wA = head1 ? wA1 : wA0;
            float wB = head1 ? wB1 : wB0;
            float wC = head1 ? wC1 : wC0;
            float wD = head1 ? wD1 : wD0;
            acc.x = fmaf(hA.x, wA, acc.x); acc.y = fmaf(hA.y, wA, acc.y);
            acc.z = fmaf(hA.z, wA, acc.z); acc.w = fmaf(hA.w, wA, acc.w);
            acc.x = fmaf(hB.x, wB, acc.x); acc.y = fmaf(hB.y, wB, acc.y);
            acc.z = fmaf(hB.z, wB, acc.z); acc.w = fmaf(hB.w, wB, acc.w);
            acc.x = fmaf(hC.x, wC, acc.x); acc.y = fmaf(hC.y, wC, acc.y);
            acc.z = fmaf(hC.z, wC, acc.z); acc.w = fmaf(hC.w, wC, acc.w);
            acc.x = fmaf(hD.x, wD, acc.x); acc.y = fmaf(hD.y, wD, acc.y);
            acc.z = fmaf(hD.z, wD, acc.z); acc.w = fmaf(hD.w, wD, acc.w);
        }
        for (; t < cnt; t++) {
            int s    = __shfl_sync(0xffffffffu, sl, t);
            float w0 = __shfl_sync(0xffffffffu, ex0, t);
            float w1 = __shfl_sync(0xffffffffu, ex1, t);
            s0 += w0; s1 += w1;
            float4 hv = reinterpret_cast<const float4*>(&g_h[(long)s * HF])[lane];
            float w = head1 ? w1 : w0;
            acc.x = fmaf(hv.x, w, acc.x);
            acc.y = fmaf(hv.y, w, acc.y);
            acc.z = fmaf(hv.z, w, acc.z);
            acc.w = fmaf(hv.w, w, acc.w);
        }
    }
    float r = head1 ? (1.f / (s1 + 1e-16f)) : (1.f / (s0 + 1e-16f));
    float4 b = reinterpret_cast<const float4*>(bias)[lane];
    float4 o;
    o.x = fmaxf(fmaf(acc.x, r, b.x), 0.f);
    o.y = fmaxf(fmaf(acc.y, r, b.y), 0.f);
    o.z = fmaxf(fmaf(acc.z, r, b.z), 0.f);
    o.w = fmaxf(fmaf(acc.w, r, b.w), 0.f);
    reinterpret_cast<float4*>(&dst[(long)n * HF])[lane] = o;
}

// ---------------- launch ------------------------------------------------------
extern "C" void kernel_launch(void* const* d_in, const int* in_sizes, int n_in,
                              void* d_out, int out_size)
{
    const float* x      = (const float*)d_in[0];
    const int*   ei     = (const int*)  d_in[1];
    const float* W1     = (const float*)d_in[2];
    const float* a_src1 = (const float*)d_in[3];
    const float* a_dst1 = (const float*)d_in[4];
    const float* b1     = (const float*)d_in[5];
    const float* W2     = (const float*)d_in[6];
    const float* a_src2 = (const float*)d_in[7];
    const float* a_dst2 = (const float*)d_in[8];
    const float* b2     = (const float*)d_in[9];
    const float* lw1    = (const float*)d_in[10];
    const float* lb1    = (const float*)d_in[11];
    const float* lw2    = (const float*)d_in[12];
    const float* lb2    = (const float*)d_in[13];
    const float* lw3    = (const float*)d_in[14];
    const float* lb3    = (const float*)d_in[15];

    int E = in_sizes[1] / 2;

    float* out    = (float*)d_out;
    float* emb    = out;                       // [N, 128]
    float* logits = out + (long)NNODES * HF;   // [N, 16]

    float *p_h, *p_h2, *p_z1;
    cudaGetSymbolAddress((void**)&p_h,  g_h);
    cudaGetSymbolAddress((void**)&p_h2, g_h2);
    cudaGetSymbolAddress((void**)&p_z1, g_z1);

    // side streams + events, created once (no device memory involved)
    static cudaStream_t sCSR = nullptr, s2 = nullptr;
    static cudaEvent_t evFork = nullptr, evCSR = nullptr, evReady = nullptr,
                       evG2h1 = nullptr, evB = nullptr, evEnd = nullptr;
    if (!sCSR) {
        cudaStreamCreateWithFlags(&sCSR, cudaStreamNonBlocking);
        cudaStreamCreateWithFlags(&s2, cudaStreamNonBlocking);
        cudaEventCreateWithFlags(&evFork, cudaEventDisableTiming);
        cudaEventCreateWithFlags(&evCSR, cudaEventDisableTiming);
        cudaEventCreateWithFlags(&evReady, cudaEventDisableTiming);
        cudaEventCreateWithFlags(&evG2h1, cudaEventDisableTiming);
        cudaEventCreateWithFlags(&evB, cudaEventDisableTiming);
        cudaEventCreateWithFlags(&evEnd, cudaEventDisableTiming);
    }

    int edgeBlocks  = cdiv(E, 256);
    int nodeBlocks  = cdiv(NNODES, 256);
    int node4Blocks = cdiv(cdiv(NNODES, 4), 256);

    const int N1 = NHALF1, N2 = NHALF2;
    int aggBlkH1 = cdiv(N1, 8), aggBlkH2 = cdiv(N2, 8);

    // ---------------- fork: logits zero + CSR build on side stream -----------
    cudaEventRecord(evFork, 0);
    cudaStreamWaitEvent(sCSR, evFork, 0);
    zero_logits_kernel<<<cdiv(NNODES * NCLS / 4, 256), 256, 0, sCSR>>>(logits);
    csr_zero_kernel<<<node4Blocks, 256, 0, sCSR>>>();
    csr_count_kernel<<<edgeBlocks, 256, 0, sCSR>>>(ei, E);
    csr_scan1_kernel<<<SCAN_NBLK, 1024, 0, sCSR>>>();
    csr_scan_fix_kernel<<<nodeBlocks, 256, 0, sCSR>>>();
    csr_scatter_kernel<<<edgeBlocks, 256, 0, sCSR>>>(ei, E);
    cudaEventRecord(evCSR, sCSR);

    // ---------------- main: GAT layer-1 GEMM (+fused alpha), full ------------
    {
        dim3 grid(1, cdiv(NNODES, 128));
        gemm_tf32_kernel<<<grid, 256>>>(x, W1, nullptr, p_h, a_src1, a_dst1,
                                        nullptr, nullptr, 0, NNODES, HF, FDIM, 0);
    }
    cudaStreamWaitEvent(0, evCSR, 0);
    cudaEventRecord(evReady, 0);
    cudaStreamWaitEvent(s2, evReady, 0);

    // ---------------- two-stream pipeline: agg1 -> gemm2 per half ------------
    agg_kernel<<<aggBlkH1, 256>>>(b1, p_h2, 0, N1);
    {
        dim3 grid(1, cdiv(N1, 128));
        gemm_tf32_kernel<<<grid, 256>>>(p_h2, W2, nullptr, p_h, a_src2, a_dst2,
                                        nullptr, nullptr, 0, N1, HF, HF, 0);
    }
    cudaEventRecord(evG2h1, 0);
    agg_kernel<<<aggBlkH2, 256, 0, s2>>>(b1, p_h2, N1, NNODES);
    {
        dim3 grid(1, cdiv(N2, 128));
        gemm_tf32_kernel<<<grid, 256, 0, s2>>>(p_h2 + (long)N1 * HF, W2, nullptr,
                                               p_h + (long)N1 * HF, a_src2, a_dst2,
                                               nullptr, nullptr, N1, N2, HF, HF, 0);
    }
    cudaEventRecord(evB, s2);

    // cross-join: agg2 on either half needs BOTH gemm2 halves
    cudaStreamWaitEvent(0, evB, 0);
    cudaStreamWaitEvent(s2, evG2h1, 0);

    // ---------------- independent tails per half ----------------
    // main: half 1
    agg_kernel<<<aggBlkH1, 256>>>(b2, emb, 0, N1);
    {
        dim3 grid(4, cdiv(N1, 128));
        gemm_tf32_kernel<<<grid, 256>>>(emb, lw1, lb1, p_z1, nullptr, nullptr,
                                        nullptr, nullptr, 0, N1, 512, HF, 1);
    }
    {
        dim3 grid(2, cdiv(N1, 128));
        gemm_tf32_kernel<<<grid, 256>>>(p_z1, lw2, lb2, nullptr, nullptr, nullptr,
                                        lw3, logits, 0, N1, 256, 512, 1);
    }

    // s2: half 2
    agg_kernel<<<aggBlkH2, 256, 0, s2>>>(b2, emb, N1, NNODES);
    {
        dim3 grid(4, cdiv(N2, 128));
        gemm_tf32_kernel<<<grid, 256, 0, s2>>>(emb + (long)N1 * HF, lw1, lb1,
                                               p_z1 + (long)N1 * 512, nullptr, nullptr,
                                               nullptr, nullptr, 0, N2, 512, HF, 1);
    }
    {
        dim3 grid(2, cdiv(N2, 128));
        gemm_tf32_kernel<<<grid, 256, 0, s2>>>(p_z1 + (long)N1 * 512, lw2, lb2,
                                               nullptr, nullptr, nullptr,
                                               lw3, logits + (long)N1 * 16,
                                               0, N2, 256, 512, 1);
    }
    cudaEventRecord(evEnd, s2);
    cudaStreamWaitEvent(0, evEnd, 0);
}

// round 15
// speedup vs baseline: 1.3843x; 1.3843x over previous
#include <cuda_runtime.h>

// Problem constants (fixed by the reference)
#define NNODES 50000
#define MAXE   1600000
#define ETOTMAX (MAXE + NNODES)
#define HF     128      // H*F
#define FDIM   64
#define NCLS   16
#define SCAN_NBLK 49    // cdiv(NNODES, 1024)
#define NHALF1 25088    // multiple of 128
#define NHALF2 (NNODES - NHALF1)

// ---------------- scratch (device globals; no allocation allowed) -------------
__device__ float    g_h[NNODES * HF];
__device__ float    g_h2[NNODES * HF];
__device__ float    g_as[NNODES * 2];
__device__ float    g_ad[NNODES * 2];
__device__ float    g_z1[NNODES * 512];
__device__ float    g_z2[NNODES * 256];
// CSR scratch
__device__ int      g_deg[NNODES];
__device__ int      g_pos[NNODES];
__device__ int      g_off[NNODES + 1];
__device__ int      g_csr[ETOTMAX];
__device__ int      g_bsum[64];

static inline int cdiv(int a, int b) { return (a + b - 1) / b; }

// ============================ CSR build ======================================
__global__ void csr_zero_kernel()
{
    int i = blockIdx.x * blockDim.x + threadIdx.x;
    int4 one = make_int4(1, 1, 1, 1);
    if (i * 4 + 3 < NNODES) {
        *reinterpret_cast<int4*>(&g_deg[i * 4]) = one;
        *reinterpret_cast<int4*>(&g_pos[i * 4]) = one;
    } else {
        for (int j = i * 4; j < NNODES; j++) { g_deg[j] = 1; g_pos[j] = 1; }
    }
}

__global__ void csr_count_kernel(const int* __restrict__ ei, int E)
{
    int i = blockIdx.x * blockDim.x + threadIdx.x;
    if (i >= E) return;
    atomicAdd(&g_deg[ei[E + i]], 1);
}

__global__ void csr_scan1_kernel()
{
    __shared__ int buf[1024];
    int t = threadIdx.x;
    int i = blockIdx.x * 1024 + t;
    int v = (i < NNODES) ? g_deg[i] : 0;
    buf[t] = v;
    __syncthreads();
#pragma unroll
    for (int off = 1; off < 1024; off <<= 1) {
        int tv = (t >= off) ? buf[t - off] : 0;
        __syncthreads();
        buf[t] += tv;
        __syncthreads();
    }
    if (i < NNODES) g_off[i + 1] = buf[t];
    if (t == 1023) g_bsum[blockIdx.x] = buf[t];
}

__global__ void csr_scan_fix_kernel()
{
    __shared__ int carry[SCAN_NBLK];
    int t = threadIdx.x;
    if (t < SCAN_NBLK) carry[t] = g_bsum[t];
    __syncthreads();
    if (t == 0) {
        int run = 0;
#pragma unroll
        for (int b = 0; b < SCAN_NBLK; b++) { int v = carry[b]; carry[b] = run; run += v; }
    }
    __syncthreads();
    int i = blockIdx.x * blockDim.x + t;
    if (i == 0) { g_off[0] = 0; g_csr[0] = 0; }
    if (i < NNODES) {
        int v = g_off[i + 1] + carry[i >> 10];
        g_off[i + 1] = v;
        if (i + 1 < NNODES) g_csr[v] = i + 1;
    }
}

__global__ void csr_scatter_kernel(const int* __restrict__ ei, int E)
{
    int i = blockIdx.x * blockDim.x + threadIdx.x;
    if (i >= E) return;
    int s = ei[i], d = ei[E + i];
    int idx = g_off[d] + atomicAdd(&g_pos[d], 1);
    g_csr[idx] = s;
}

// ============================ tf32 helpers ===================================
__device__ __forceinline__ unsigned f2tf32(float f)
{
    unsigned r;
    asm("cvt.rna.tf32.f32 %0, %1;" : "=r"(r) : "f"(f));
    return r;
}

__device__ __forceinline__ void mma_tf32(float c[4], const unsigned a[4],
                                         unsigned b0, unsigned b1)
{
    asm volatile(
        "mma.sync.aligned.m16n8k8.row.col.f32.tf32.tf32.f32 "
        "{%0,%1,%2,%3},{%4,%5,%6,%7},{%8,%9},{%0,%1,%2,%3};"
        : "+f"(c[0]), "+f"(c[1]), "+f"(c[2]), "+f"(c[3])
        : "r"(a[0]), "r"(a[1]), "r"(a[2]), "r"(a[3]), "r"(b0), "r"(b1));
}

// ===== shared GEMM body (device inline); caller provides epilogue flavor =====
struct GemmCtx {
    float acc[2][8][4];
    int row0, col0, wr, wc, g, tig;
};

__device__ __forceinline__ void gemm_mainloop(
    GemmCtx& ctx,
    const float* __restrict__ A, const float* __restrict__ B,
    int M, int Nn, int K)
{
    __shared__ float As[2][16][132];
    __shared__ float Bs[2][16][132];

    int tid = threadIdx.x;
    int lane = tid & 31, wid = tid >> 5;
    ctx.wr = wid >> 1; ctx.wc = wid & 1;
    ctx.row0 = blockIdx.y * 128; ctx.col0 = blockIdx.x * 128;
    ctx.g = lane >> 2; ctx.tig = lane & 3;

#pragma unroll
    for (int mi = 0; mi < 2; mi++)
#pragma unroll
        for (int ni = 0; ni < 8; ni++)
#pragma unroll
            for (int q = 0; q < 4; q++) ctx.acc[mi][ni][q] = 0.f;

    int ar = tid >> 2;
    int akc = (tid & 3) * 4;
    int bkr = tid >> 5;
    int bnc = (tid & 31) * 4;

    float4 ra[2], rb[2];

    auto load_tiles = [&](int k0) {
#pragma unroll
        for (int rr = 0; rr < 2; rr++) {
            int grow = ctx.row0 + ar + rr * 64;
            ra[rr] = make_float4(0.f, 0.f, 0.f, 0.f);
            if (grow < M)
                ra[rr] = *reinterpret_cast<const float4*>(&A[(long)grow * K + k0 + akc]);
        }
#pragma unroll
        for (int rr = 0; rr < 2; rr++) {
            int kr = k0 + bkr + rr * 8;
            rb[rr] = *reinterpret_cast<const float4*>(&B[(long)kr * Nn + ctx.col0 + bnc]);
        }
    };

    auto store_tiles = [&](int buf) {
#pragma unroll
        for (int rr = 0; rr < 2; rr++) {
            As[buf][akc + 0][ar + rr * 64] = __uint_as_float(f2tf32(ra[rr].x));
            As[buf][akc + 1][ar + rr * 64] = __uint_as_float(f2tf32(ra[rr].y));
            As[buf][akc + 2][ar + rr * 64] = __uint_as_float(f2tf32(ra[rr].z));
            As[buf][akc + 3][ar + rr * 64] = __uint_as_float(f2tf32(ra[rr].w));
        }
#pragma unroll
        for (int rr = 0; rr < 2; rr++) {
            float4 t;
            t.x = __uint_as_float(f2tf32(rb[rr].x));
            t.y = __uint_as_float(f2tf32(rb[rr].y));
            t.z = __uint_as_float(f2tf32(rb[rr].z));
            t.w = __uint_as_float(f2tf32(rb[rr].w));
            *reinterpret_cast<float4*>(&Bs[buf][bkr + rr * 8][bnc]) = t;
        }
    };

    int nk = K >> 4;
    load_tiles(0);
    store_tiles(0);
    __syncthreads();

    for (int it = 0; it < nk; it++) {
        int cur = it & 1;
        bool has_next = (it + 1 < nk);
        if (has_next) load_tiles((it + 1) << 4);

#pragma unroll
        for (int ks = 0; ks < 16; ks += 8) {
            unsigned af[2][4];
#pragma unroll
            for (int mi = 0; mi < 2; mi++) {
                int mb = ctx.wr * 32 + mi * 16 + ctx.g;
                af[mi][0] = __float_as_uint(As[cur][ks + ctx.tig][mb]);
                af[mi][1] = __float_as_uint(As[cur][ks + ctx.tig][mb + 8]);
                af[mi][2] = __float_as_uint(As[cur][ks + ctx.tig + 4][mb]);
                af[mi][3] = __float_as_uint(As[cur][ks + ctx.tig + 4][mb + 8]);
            }
#pragma unroll
            for (int ni = 0; ni < 8; ni++) {
                int nb = ctx.wc * 64 + ni * 8 + ctx.g;
                unsigned b0 = __float_as_uint(Bs[cur][ks + ctx.tig][nb]);
                unsigned b1 = __float_as_uint(Bs[cur][ks + ctx.tig + 4][nb]);
                mma_tf32(ctx.acc[0][ni], af[0], b0, b1);
                mma_tf32(ctx.acc[1][ni], af[1], b0, b1);
            }
        }

        if (has_next) store_tiles(cur ^ 1);
        __syncthreads();
    }
}

__device__ __forceinline__ void gemm_store_c(
    GemmCtx& ctx, const float* __restrict__ bias, float* __restrict__ C,
    int M, int Nn, int doRelu)
{
#pragma unroll
    for (int mi = 0; mi < 2; mi++) {
#pragma unroll
        for (int ni = 0; ni < 8; ni++) {
            int r0 = ctx.row0 + ctx.wr * 32 + mi * 16 + ctx.g;
            int c0 = ctx.col0 + ctx.wc * 64 + ni * 8 + 2 * ctx.tig;
#pragma unroll
            for (int half = 0; half < 2; half++) {
                int gr = r0 + half * 8;
                if (gr >= M) continue;
                float v0 = ctx.acc[mi][ni][half * 2 + 0];
                float v1 = ctx.acc[mi][ni][half * 2 + 1];
                if (bias) { v0 += bias[c0]; v1 += bias[c0 + 1]; }
                if (doRelu) { v0 = fmaxf(v0, 0.f); v1 = fmaxf(v1, 0.f); }
                C[(long)gr * Nn + c0] = v0;
                C[(long)gr * Nn + c0 + 1] = v1;
            }
        }
    }
}

// ---- plain GEMM kernel (MLP layers): lean register budget -------------------
__global__ __launch_bounds__(256) void gemm_tf32_kernel(
    const float* __restrict__ A, const float* __restrict__ B,
    const float* __restrict__ bias, float* __restrict__ C,
    int M, int Nn, int K, int doRelu)
{
    GemmCtx ctx;
    gemm_mainloop(ctx, A, B, M, Nn, K);
    gemm_store_c(ctx, bias, C, M, Nn, doRelu);
}

// ---- GAT GEMM kernel: plain epilogue + fused alpha dot products -------------
__global__ __launch_bounds__(256) void gemm_tf32_alpha_kernel(
    const float* __restrict__ A, const float* __restrict__ B,
    float* __restrict__ C,
    const float* __restrict__ alpha_src, const float* __restrict__ alpha_dst,
    int rowBase, int M, int Nn, int K)
{
    GemmCtx ctx;
    gemm_mainloop(ctx, A, B, M, Nn, K);
    gemm_store_c(ctx, nullptr, C, M, Nn, 0);

    float cs[8][2], cd[8][2];
#pragma unroll
    for (int ni = 0; ni < 8; ni++) {
        int c = ctx.wc * 64 + ni * 8 + 2 * ctx.tig;
        cs[ni][0] = alpha_src[c];     cs[ni][1] = alpha_src[c + 1];
        cd[ni][0] = alpha_dst[c];     cd[ni][1] = alpha_dst[c + 1];
    }
#pragma unroll
    for (int mi = 0; mi < 2; mi++) {
#pragma unroll
        for (int half = 0; half < 2; half++) {
            float ps = 0.f, pd = 0.f;
#pragma unroll
            for (int ni = 0; ni < 8; ni++) {
                float v0 = ctx.acc[mi][ni][half * 2 + 0];
                float v1 = ctx.acc[mi][ni][half * 2 + 1];
                ps = fmaf(v0, cs[ni][0], fmaf(v1, cs[ni][1], ps));
                pd = fmaf(v0, cd[ni][0], fmaf(v1, cd[ni][1], pd));
            }
            ps += __shfl_down_sync(0xffffffffu, ps, 1, 4);
            ps += __shfl_down_sync(0xffffffffu, ps, 2, 4);
            pd += __shfl_down_sync(0xffffffffu, pd, 1, 4);
            pd += __shfl_down_sync(0xffffffffu, pd, 2, 4);
            int gr = ctx.row0 + ctx.wr * 32 + mi * 16 + ctx.g + half * 8;
            if (ctx.tig == 0 && gr < M) {
                g_as[(rowBase + gr) * 2 + ctx.wc] = ps;
                g_ad[(rowBase + gr) * 2 + ctx.wc] = pd;
            }
        }
    }
}

// ============================ tf32 GEMM, N = 16 ==============================
__global__ __launch_bounds__(256) void gemm_tf32_n16_kernel(
    const float* __restrict__ A, const float* __restrict__ B,
    const float* __restrict__ bias, float* __restrict__ C,
    int M, int K)
{
    __shared__ float As[32][132];
    __shared__ float Bs[32][20];

    int tid = threadIdx.x;
    int lane = tid & 31, wid = tid >> 5;
    int g = lane >> 2, tig = lane & 3;
    int row0 = blockIdx.x * 128;

    float acc[2][4];
#pragma unroll
    for (int ni = 0; ni < 2; ni++)
#pragma unroll
        for (int q = 0; q < 4; q++) acc[ni][q] = 0.f;

    int ar = tid >> 1;
    int akc0 = (tid & 1) * 16;
    int bk = tid >> 3;
    int bn = (tid & 7) * 2;

    for (int k0 = 0; k0 < K; k0 += 32) {
        int gr = row0 + ar;
#pragma unroll
        for (int q = 0; q < 4; q++) {
            int kc = akc0 + q * 4;
            float4 v = make_float4(0.f, 0.f, 0.f, 0.f);
            if (gr < M) v = *reinterpret_cast<const float4*>(&A[(long)gr * K + k0 + kc]);
            As[kc + 0][ar] = __uint_as_float(f2tf32(v.x));
            As[kc + 1][ar] = __uint_as_float(f2tf32(v.y));
            As[kc + 2][ar] = __uint_as_float(f2tf32(v.z));
            As[kc + 3][ar] = __uint_as_float(f2tf32(v.w));
        }
        Bs[bk][bn]     = __uint_as_float(f2tf32(B[(long)(k0 + bk) * 16 + bn]));
        Bs[bk][bn + 1] = __uint_as_float(f2tf32(B[(long)(k0 + bk) * 16 + bn + 1]));
        __syncthreads();

#pragma unroll
        for (int ks = 0; ks < 32; ks += 8) {
            int mb = wid * 16 + g;
            unsigned a[4];
            a[0] = __float_as_uint(As[ks + tig][mb]);
            a[1] = __float_as_uint(As[ks + tig][mb + 8]);
            a[2] = __float_as_uint(As[ks + tig + 4][mb]);
            a[3] = __float_as_uint(As[ks + tig + 4][mb + 8]);
#pragma unroll
            for (int ni = 0; ni < 2; ni++) {
                unsigned b0 = __float_as_uint(Bs[ks + tig][ni * 8 + g]);
                unsigned b1 = __float_as_uint(Bs[ks + tig + 4][ni * 8 + g]);
                mma_tf32(acc[ni], a, b0, b1);
            }
        }
        __syncthreads();
    }

#pragma unroll
    for (int ni = 0; ni < 2; ni++) {
        int c0 = ni * 8 + 2 * tig;
#pragma unroll
        for (int half = 0; half < 2; half++) {
            int gr = row0 + wid * 16 + g + half * 8;
            if (gr >= M) continue;
            C[(long)gr * 16 + c0]     = acc[ni][half * 2 + 0] + bias[c0];
            C[(long)gr * 16 + c0 + 1] = acc[ni][half * 2 + 1] + bias[c0 + 1];
        }
    }
}

// ---------------- fused softmax + aggregation over node range [n0, n1) -------
__global__ void agg_kernel(const float* __restrict__ bias, float* __restrict__ dst,
                           int n0, int n1)
{
    int n = n0 + ((blockIdx.x * blockDim.x + threadIdx.x) >> 5);
    int lane = threadIdx.x & 31;
    if (n >= n1) return;
    int beg = g_off[n], end = g_off[n + 1];
    float ad0 = g_ad[n * 2 + 0], ad1 = g_ad[n * 2 + 1];
    int head1 = lane >= 16;

    float4 acc = make_float4(0.f, 0.f, 0.f, 0.f);
    float s0 = 0.f, s1 = 0.f;

    for (int base = beg; base < end; base += 32) {
        int cnt = min(32, end - base);
        int sl = 0; float ex0 = 0.f, ex1 = 0.f;
        if (lane < cnt) {
            sl = g_csr[base + lane];
            float2 a = *reinterpret_cast<const float2*>(&g_as[sl * 2]);
            float e0 = a.x + ad0; e0 = fmaxf(e0, 0.2f * e0);
            float e1 = a.y + ad1; e1 = fmaxf(e1, 0.2f * e1);
            ex0 = __expf(e0);
            ex1 = __expf(e1);
        }
        int t = 0;
        for (; t + 4 <= cnt; t += 4) {
            int   sA = __shfl_sync(0xffffffffu, sl, t + 0);
            int   sB = __shfl_sync(0xffffffffu, sl, t + 1);
            int   sC = __shfl_sync(0xffffffffu, sl, t + 2);
            int   sD = __shfl_sync(0xffffffffu, sl, t + 3);
            float wA0 = __shfl_sync(0xffffffffu, ex0, t + 0);
            float wB0 = __shfl_sync(0xffffffffu, ex0, t + 1);
            float wC0 = __shfl_sync(0xffffffffu, ex0, t + 2);
            float wD0 = __shfl_sync(0xffffffffu, ex0, t + 3);
            float wA1 = __shfl_sync(0xffffffffu, ex1, t + 0);
            float wB1 = __shfl_sync(0xffffffffu, ex1, t + 1);
            float wC1 = __shfl_sync(0xffffffffu, ex1, t + 2);
            float wD1 = __shfl_sync(0xffffffffu, ex1, t + 3);
            float4 hA = reinterpret_cast<const float4*>(&g_h[(long)sA * HF])[lane];
            float4 hB = reinterpret_cast<const float4*>(&g_h[(long)sB * HF])[lane];
            float4 hC = reinterpret_cast<const float4*>(&g_h[(long)sC * HF])[lane];
            float4 hD = reinterpret_cast<const float4*>(&g_h[(long)sD * HF])[lane];
            s0 += wA0 + wB0 + wC0 + wD0;
            s1 += wA1 + wB1 + wC1 + wD1;
            float wA = head1 ? wA1 : wA0;
            float wB = head1 ? wB1 : wB0;
            float wC = head1 ? wC1 : wC0;
            float wD = head1 ? wD1 : wD0;
            acc.x = fmaf(hA.x, wA, acc.x); acc.y = fmaf(hA.y, wA, acc.y);
            acc.z = fmaf(hA.z, wA, acc.z); acc.w = fmaf(hA.w, wA, acc.w);
            acc.x = fmaf(hB.x, wB, acc.x); acc.y = fmaf(hB.y, wB, acc.y);
            acc.z = fmaf(hB.z, wB, acc.z); acc.w = fmaf(hB.w, wB, acc.w);
            acc.x = fmaf(hC.x, wC, acc.x); acc.y = fmaf(hC.y, wC, acc.y);
            acc.z = fmaf(hC.z, wC, acc.z); acc.w = fmaf(hC.w, wC, acc.w);
            acc.x = fmaf(hD.x, wD, acc.x); acc.y = fmaf(hD.y, wD, acc.y);
            acc.z = fmaf(hD.z, wD, acc.z); acc.w = fmaf(hD.w, wD, acc.w);
        }
        for (; t < cnt; t++) {
            int s    = __shfl_sync(0xffffffffu, sl, t);
            float w0 = __shfl_sync(0xffffffffu, ex0, t);
            float w1 = __shfl_sync(0xffffffffu, ex1, t);
            s0 += w0; s1 += w1;
            float4 hv = reinterpret_cast<const float4*>(&g_h[(long)s * HF])[lane];
            float w = head1 ? w1 : w0;
            acc.x = fmaf(hv.x, w, acc.x);
            acc.y = fmaf(hv.y, w, acc.y);
            acc.z = fmaf(hv.z, w, acc.z);
            acc.w = fmaf(hv.w, w, acc.w);
        }
    }
    float r = head1 ? (1.f / (s1 + 1e-16f)) : (1.f / (s0 + 1e-16f));
    float4 b = reinterpret_cast<const float4*>(bias)[lane];
    float4 o;
    o.x = fmaxf(fmaf(acc.x, r, b.x), 0.f);
    o.y = fmaxf(fmaf(acc.y, r, b.y), 0.f);
    o.z = fmaxf(fmaf(acc.z, r, b.z), 0.f);
    o.w = fmaxf(fmaf(acc.w, r, b.w), 0.f);
    reinterpret_cast<float4*>(&dst[(long)n * HF])[lane] = o;
}

// ---------------- launch ------------------------------------------------------
extern "C" void kernel_launch(void* const* d_in, const int* in_sizes, int n_in,
                              void* d_out, int out_size)
{
    const float* x      = (const float*)d_in[0];
    const int*   ei     = (const int*)  d_in[1];
    const float* W1     = (const float*)d_in[2];
    const float* a_src1 = (const float*)d_in[3];
    const float* a_dst1 = (const float*)d_in[4];
    const float* b1     = (const float*)d_in[5];
    const float* W2     = (const float*)d_in[6];
    const float* a_src2 = (const float*)d_in[7];
    const float* a_dst2 = (const float*)d_in[8];
    const float* b2     = (const float*)d_in[9];
    const float* lw1    = (const float*)d_in[10];
    const float* lb1    = (const float*)d_in[11];
    const float* lw2    = (const float*)d_in[12];
    const float* lb2    = (const float*)d_in[13];
    const float* lw3    = (const float*)d_in[14];
    const float* lb3    = (const float*)d_in[15];

    int E = in_sizes[1] / 2;

    float* out    = (float*)d_out;
    float* emb    = out;                       // [N, 128]
    float* logits = out + (long)NNODES * HF;   // [N, 16]

    float *p_h, *p_h2, *p_z1, *p_z2;
    cudaGetSymbolAddress((void**)&p_h,  g_h);
    cudaGetSymbolAddress((void**)&p_h2, g_h2);
    cudaGetSymbolAddress((void**)&p_z1, g_z1);
    cudaGetSymbolAddress((void**)&p_z2, g_z2);

    // side streams + events, created once (no device memory involved)
    static cudaStream_t sCSR = nullptr, s2 = nullptr;
    static cudaEvent_t evFork = nullptr, evCSR = nullptr, evReady = nullptr,
                       evG2h1 = nullptr, evB = nullptr, evEnd = nullptr;
    if (!sCSR) {
        cudaStreamCreateWithFlags(&sCSR, cudaStreamNonBlocking);
        cudaStreamCreateWithFlags(&s2, cudaStreamNonBlocking);
        cudaEventCreateWithFlags(&evFork, cudaEventDisableTiming);
        cudaEventCreateWithFlags(&evCSR, cudaEventDisableTiming);
        cudaEventCreateWithFlags(&evReady, cudaEventDisableTiming);
        cudaEventCreateWithFlags(&evG2h1, cudaEventDisableTiming);
        cudaEventCreateWithFlags(&evB, cudaEventDisableTiming);
        cudaEventCreateWithFlags(&evEnd, cudaEventDisableTiming);
    }

    int edgeBlocks  = cdiv(E, 256);
    int nodeBlocks  = cdiv(NNODES, 256);
    int node4Blocks = cdiv(cdiv(NNODES, 4), 256);

    const int N1 = NHALF1, N2 = NHALF2;
    int aggBlkH1 = cdiv(N1, 8), aggBlkH2 = cdiv(N2, 8);

    // ---------------- fork: CSR build on side stream ----------------
    cudaEventRecord(evFork, 0);
    cudaStreamWaitEvent(sCSR, evFork, 0);
    csr_zero_kernel<<<node4Blocks, 256, 0, sCSR>>>();
    csr_count_kernel<<<edgeBlocks, 256, 0, sCSR>>>(ei, E);
    csr_scan1_kernel<<<SCAN_NBLK, 1024, 0, sCSR>>>();
    csr_scan_fix_kernel<<<nodeBlocks, 256, 0, sCSR>>>();
    csr_scatter_kernel<<<edgeBlocks, 256, 0, sCSR>>>(ei, E);
    cudaEventRecord(evCSR, sCSR);

    // ---------------- main: GAT layer-1 GEMM (+fused alpha), full ------------
    {
        dim3 grid(1, cdiv(NNODES, 128));
        gemm_tf32_alpha_kernel<<<grid, 256>>>(x, W1, p_h, a_src1, a_dst1,
                                              0, NNODES, HF, FDIM);
    }
    cudaStreamWaitEvent(0, evCSR, 0);
    cudaEventRecord(evReady, 0);
    cudaStreamWaitEvent(s2, evReady, 0);

    // ---------------- two-stream pipeline: agg1 -> gemm2 per half ------------
    agg_kernel<<<aggBlkH1, 256>>>(b1, p_h2, 0, N1);
    {
        dim3 grid(1, cdiv(N1, 128));
        gemm_tf32_alpha_kernel<<<grid, 256>>>(p_h2, W2, p_h, a_src2, a_dst2,
                                              0, N1, HF, HF);
    }
    cudaEventRecord(evG2h1, 0);
    agg_kernel<<<aggBlkH2, 256, 0, s2>>>(b1, p_h2, N1, NNODES);
    {
        dim3 grid(1, cdiv(N2, 128));
        gemm_tf32_alpha_kernel<<<grid, 256, 0, s2>>>(p_h2 + (long)N1 * HF, W2,
                                                     p_h + (long)N1 * HF,
                                                     a_src2, a_dst2,
                                                     N1, N2, HF, HF);
    }
    cudaEventRecord(evB, s2);

    // cross-join: agg2 on either half needs BOTH gemm2 halves
    cudaStreamWaitEvent(0, evB, 0);
    cudaStreamWaitEvent(s2, evG2h1, 0);

    // ---------------- independent tails per half ----------------
    // main: half 1
    agg_kernel<<<aggBlkH1, 256>>>(b2, emb, 0, N1);
    {
        dim3 grid(4, cdiv(N1, 128));
        gemm_tf32_kernel<<<grid, 256>>>(emb, lw1, lb1, p_z1, N1, 512, HF, 1);
    }
    {
        dim3 grid(2, cdiv(N1, 128));
        gemm_tf32_kernel<<<grid, 256>>>(p_z1, lw2, lb2, p_z2, N1, 256, 512, 1);
    }
    gemm_tf32_n16_kernel<<<cdiv(N1, 128), 256>>>(p_z2, lw3, lb3, logits, N1, 256);

    // s2: half 2
    agg_kernel<<<aggBlkH2, 256, 0, s2>>>(b2, emb, N1, NNODES);
    {
        dim3 grid(4, cdiv(N2, 128));
        gemm_tf32_kernel<<<grid, 256, 0, s2>>>(emb + (long)N1 * HF, lw1, lb1,
                                               p_z1 + (long)N1 * 512, N2, 512, HF, 1);
    }
    {
        dim3 grid(2, cdiv(N2, 128));
        gemm_tf32_kernel<<<grid, 256, 0, s2>>>(p_z1 + (long)N1 * 512, lw2, lb2,
                                               p_z2 + (long)N1 * 256, N2, 256, 512, 1);
    }
    gemm_tf32_n16_kernel<<<cdiv(N2, 128), 256, 0, s2>>>(p_z2 + (long)N1 * 256, lw3, lb3,
                                                        logits + (long)N1 * 16, N2, 256);
    cudaEventRecord(evEnd, s2);
    cudaStreamWaitEvent(0, evEnd, 0);
}

// round 17
// speedup vs baseline: 1.4088x; 1.0177x over previous
#include <cuda_runtime.h>
#include <cuda_fp16.h>

// Problem constants (fixed by the reference)
#define NNODES 50000
#define MAXE   1600000
#define ETOTMAX (MAXE + NNODES)
#define HF     128      // H*F
#define FDIM   64
#define NCLS   16
#define SCAN_NBLK 49    // cdiv(NNODES, 1024)
#define NHALF1 25088    // multiple of 128
#define NHALF2 (NNODES - NHALF1)

// ---------------- scratch (device globals; no allocation allowed) -------------
__device__ __half   g_hh[NNODES * HF];   // fp16 message mirror (agg gathers)
__device__ float    g_h2[NNODES * HF];
__device__ float    g_as[NNODES * 2];
__device__ float    g_ad[NNODES * 2];
__device__ float    g_z1[NNODES * 512];
__device__ float    g_z2[NNODES * 256];
// CSR scratch
__device__ int      g_deg[NNODES];
__device__ int      g_pos[NNODES];
__device__ int      g_off[NNODES + 1];
__device__ int      g_csr[ETOTMAX];
__device__ int      g_bsum[64];

static inline int cdiv(int a, int b) { return (a + b - 1) / b; }

// ============================ CSR build ======================================
__global__ void csr_zero_kernel()
{
    int i = blockIdx.x * blockDim.x + threadIdx.x;
    int4 one = make_int4(1, 1, 1, 1);
    if (i * 4 + 3 < NNODES) {
        *reinterpret_cast<int4*>(&g_deg[i * 4]) = one;
        *reinterpret_cast<int4*>(&g_pos[i * 4]) = one;
    } else {
        for (int j = i * 4; j < NNODES; j++) { g_deg[j] = 1; g_pos[j] = 1; }
    }
}

__global__ void csr_count_kernel(const int* __restrict__ ei, int E)
{
    int i = blockIdx.x * blockDim.x + threadIdx.x;
    if (i >= E) return;
    atomicAdd(&g_deg[ei[E + i]], 1);
}

__global__ void csr_scan1_kernel()
{
    __shared__ int buf[1024];
    int t = threadIdx.x;
    int i = blockIdx.x * 1024 + t;
    int v = (i < NNODES) ? g_deg[i] : 0;
    buf[t] = v;
    __syncthreads();
#pragma unroll
    for (int off = 1; off < 1024; off <<= 1) {
        int tv = (t >= off) ? buf[t - off] : 0;
        __syncthreads();
        buf[t] += tv;
        __syncthreads();
    }
    if (i < NNODES) g_off[i + 1] = buf[t];
    if (t == 1023) g_bsum[blockIdx.x] = buf[t];
}

__global__ void csr_scan_fix_kernel()
{
    __shared__ int carry[SCAN_NBLK];
    int t = threadIdx.x;
    if (t < SCAN_NBLK) carry[t] = g_bsum[t];
    __syncthreads();
    if (t == 0) {
        int run = 0;
#pragma unroll
        for (int b = 0; b < SCAN_NBLK; b++) { int v = carry[b]; carry[b] = run; run += v; }
    }
    __syncthreads();
    int i = blockIdx.x * blockDim.x + t;
    if (i == 0) { g_off[0] = 0; g_csr[0] = 0; }
    if (i < NNODES) {
        int v = g_off[i + 1] + carry[i >> 10];
        g_off[i + 1] = v;
        if (i + 1 < NNODES) g_csr[v] = i + 1;
    }
}

__global__ void csr_scatter_kernel(const int* __restrict__ ei, int E)
{
    int i = blockIdx.x * blockDim.x + threadIdx.x;
    if (i >= E) return;
    int s = ei[i], d = ei[E + i];
    int idx = g_off[d] + atomicAdd(&g_pos[d], 1);
    g_csr[idx] = s;
}

// ============================ tf32 helpers ===================================
__device__ __forceinline__ unsigned f2tf32(float f)
{
    unsigned r;
    asm("cvt.rna.tf32.f32 %0, %1;" : "=r"(r) : "f"(f));
    return r;
}

__device__ __forceinline__ void mma_tf32(float c[4], const unsigned a[4],
                                         unsigned b0, unsigned b1)
{
    asm volatile(
        "mma.sync.aligned.m16n8k8.row.col.f32.tf32.tf32.f32 "
        "{%0,%1,%2,%3},{%4,%5,%6,%7},{%8,%9},{%0,%1,%2,%3};"
        : "+f"(c[0]), "+f"(c[1]), "+f"(c[2]), "+f"(c[3])
        : "r"(a[0]), "r"(a[1]), "r"(a[2]), "r"(a[3]), "r"(b0), "r"(b1));
}

// ===== shared GEMM body (device inline); caller provides epilogue flavor =====
struct GemmCtx {
    float acc[2][8][4];
    int row0, col0, wr, wc, g, tig;
};

__device__ __forceinline__ void gemm_mainloop(
    GemmCtx& ctx,
    const float* __restrict__ A, const float* __restrict__ B,
    int M, int Nn, int K)
{
    __shared__ float As[2][16][132];
    __shared__ float Bs[2][16][132];

    int tid = threadIdx.x;
    int lane = tid & 31, wid = tid >> 5;
    ctx.wr = wid >> 1; ctx.wc = wid & 1;
    ctx.row0 = blockIdx.y * 128; ctx.col0 = blockIdx.x * 128;
    ctx.g = lane >> 2; ctx.tig = lane & 3;

#pragma unroll
    for (int mi = 0; mi < 2; mi++)
#pragma unroll
        for (int ni = 0; ni < 8; ni++)
#pragma unroll
            for (int q = 0; q < 4; q++) ctx.acc[mi][ni][q] = 0.f;

    int ar = tid >> 2;
    int akc = (tid & 3) * 4;
    int bkr = tid >> 5;
    int bnc = (tid & 31) * 4;

    float4 ra[2], rb[2];

    auto load_tiles = [&](int k0) {
#pragma unroll
        for (int rr = 0; rr < 2; rr++) {
            int grow = ctx.row0 + ar + rr * 64;
            ra[rr] = make_float4(0.f, 0.f, 0.f, 0.f);
            if (grow < M)
                ra[rr] = *reinterpret_cast<const float4*>(&A[(long)grow * K + k0 + akc]);
        }
#pragma unroll
        for (int rr = 0; rr < 2; rr++) {
            int kr = k0 + bkr + rr * 8;
            rb[rr] = *reinterpret_cast<const float4*>(&B[(long)kr * Nn + ctx.col0 + bnc]);
        }
    };

    auto store_tiles = [&](int buf) {
#pragma unroll
        for (int rr = 0; rr < 2; rr++) {
            As[buf][akc + 0][ar + rr * 64] = __uint_as_float(f2tf32(ra[rr].x));
            As[buf][akc + 1][ar + rr * 64] = __uint_as_float(f2tf32(ra[rr].y));
            As[buf][akc + 2][ar + rr * 64] = __uint_as_float(f2tf32(ra[rr].z));
            As[buf][akc + 3][ar + rr * 64] = __uint_as_float(f2tf32(ra[rr].w));
        }
#pragma unroll
        for (int rr = 0; rr < 2; rr++) {
            float4 t;
            t.x = __uint_as_float(f2tf32(rb[rr].x));
            t.y = __uint_as_float(f2tf32(rb[rr].y));
            t.z = __uint_as_float(f2tf32(rb[rr].z));
            t.w = __uint_as_float(f2tf32(rb[rr].w));
            *reinterpret_cast<float4*>(&Bs[buf][bkr + rr * 8][bnc]) = t;
        }
    };

    int nk = K >> 4;
    load_tiles(0);
    store_tiles(0);
    __syncthreads();

    for (int it = 0; it < nk; it++) {
        int cur = it & 1;
        bool has_next = (it + 1 < nk);
        if (has_next) load_tiles((it + 1) << 4);

#pragma unroll
        for (int ks = 0; ks < 16; ks += 8) {
            unsigned af[2][4];
#pragma unroll
            for (int mi = 0; mi < 2; mi++) {
                int mb = ctx.wr * 32 + mi * 16 + ctx.g;
                af[mi][0] = __float_as_uint(As[cur][ks + ctx.tig][mb]);
                af[mi][1] = __float_as_uint(As[cur][ks + ctx.tig][mb + 8]);
                af[mi][2] = __float_as_uint(As[cur][ks + ctx.tig + 4][mb]);
                af[mi][3] = __float_as_uint(As[cur][ks + ctx.tig + 4][mb + 8]);
            }
#pragma unroll
            for (int ni = 0; ni < 8; ni++) {
                int nb = ctx.wc * 64 + ni * 8 + ctx.g;
                unsigned b0 = __float_as_uint(Bs[cur][ks + ctx.tig][nb]);
                unsigned b1 = __float_as_uint(Bs[cur][ks + ctx.tig + 4][nb]);
                mma_tf32(ctx.acc[0][ni], af[0], b0, b1);
                mma_tf32(ctx.acc[1][ni], af[1], b0, b1);
            }
        }

        if (has_next) store_tiles(cur ^ 1);
        __syncthreads();
    }
}

__device__ __forceinline__ void gemm_store_c(
    GemmCtx& ctx, const float* __restrict__ bias, float* __restrict__ C,
    int M, int Nn, int doRelu)
{
#pragma unroll
    for (int mi = 0; mi < 2; mi++) {
#pragma unroll
        for (int ni = 0; ni < 8; ni++) {
            int r0 = ctx.row0 + ctx.wr * 32 + mi * 16 + ctx.g;
            int c0 = ctx.col0 + ctx.wc * 64 + ni * 8 + 2 * ctx.tig;
#pragma unroll
            for (int half = 0; half < 2; half++) {
                int gr = r0 + half * 8;
                if (gr >= M) continue;
                float v0 = ctx.acc[mi][ni][half * 2 + 0];
                float v1 = ctx.acc[mi][ni][half * 2 + 1];
                if (bias) { v0 += bias[c0]; v1 += bias[c0 + 1]; }
                if (doRelu) { v0 = fmaxf(v0, 0.f); v1 = fmaxf(v1, 0.f); }
                C[(long)gr * Nn + c0] = v0;
                C[(long)gr * Nn + c0 + 1] = v1;
            }
        }
    }
}

// ---- plain GEMM kernel (MLP layers): lean register budget -------------------
__global__ __launch_bounds__(256) void gemm_tf32_kernel(
    const float* __restrict__ A, const float* __restrict__ B,
    const float* __restrict__ bias, float* __restrict__ C,
    int M, int Nn, int K, int doRelu)
{
    GemmCtx ctx;
    gemm_mainloop(ctx, A, B, M, Nn, K);
    gemm_store_c(ctx, bias, C, M, Nn, doRelu);
}

// ---- GAT GEMM kernel: fp16 message store + fused alpha dot products ---------
// h is stored ONLY as fp16 (agg is its sole consumer); alpha dots use the
// exact fp32 accumulators. rowBase maps local rows to global node ids.
__global__ __launch_bounds__(256) void gemm_tf32_alpha_kernel(
    const float* __restrict__ A, const float* __restrict__ B,
    const float* __restrict__ alpha_src, const float* __restrict__ alpha_dst,
    int rowBase, int M, int Nn, int K)
{
    GemmCtx ctx;
    gemm_mainloop(ctx, A, B, M, Nn, K);

    // fp16 mirror store (gridDim.x == 1, so this block owns full rows)
#pragma unroll
    for (int mi = 0; mi < 2; mi++) {
#pragma unroll
        for (int ni = 0; ni < 8; ni++) {
            int r0 = ctx.row0 + ctx.wr * 32 + mi * 16 + ctx.g;
            int c0 = ctx.wc * 64 + ni * 8 + 2 * ctx.tig;
#pragma unroll
            for (int half = 0; half < 2; half++) {
                int gr = r0 + half * 8;
                if (gr >= M) continue;
                __half2 p;
                p.x = __float2half_rn(ctx.acc[mi][ni][half * 2 + 0]);
                p.y = __float2half_rn(ctx.acc[mi][ni][half * 2 + 1]);
                *reinterpret_cast<__half2*>(&g_hh[(long)(rowBase + gr) * HF + c0]) = p;
            }
        }
    }

    // fused alpha epilogue
    float cs[8][2], cd[8][2];
#pragma unroll
    for (int ni = 0; ni < 8; ni++) {
        int c = ctx.wc * 64 + ni * 8 + 2 * ctx.tig;
        cs[ni][0] = alpha_src[c];     cs[ni][1] = alpha_src[c + 1];
        cd[ni][0] = alpha_dst[c];     cd[ni][1] = alpha_dst[c + 1];
    }
#pragma unroll
    for (int mi = 0; mi < 2; mi++) {
#pragma unroll
        for (int half = 0; half < 2; half++) {
            float ps = 0.f, pd = 0.f;
#pragma unroll
            for (int ni = 0; ni < 8; ni++) {
                float v0 = ctx.acc[mi][ni][half * 2 + 0];
                float v1 = ctx.acc[mi][ni][half * 2 + 1];
                ps = fmaf(v0, cs[ni][0], fmaf(v1, cs[ni][1], ps));
                pd = fmaf(v0, cd[ni][0], fmaf(v1, cd[ni][1], pd));
            }
            ps += __shfl_down_sync(0xffffffffu, ps, 1, 4);
            ps += __shfl_down_sync(0xffffffffu, ps, 2, 4);
            pd += __shfl_down_sync(0xffffffffu, pd, 1, 4);
            pd += __shfl_down_sync(0xffffffffu, pd, 2, 4);
            int gr = ctx.row0 + ctx.wr * 32 + mi * 16 + ctx.g + half * 8;
            if (ctx.tig == 0 && gr < M) {
                g_as[(rowBase + gr) * 2 + ctx.wc] = ps;
                g_ad[(rowBase + gr) * 2 + ctx.wc] = pd;
            }
        }
    }
}

// ============================ tf32 GEMM, N = 16 ==============================
__global__ __launch_bounds__(256) void gemm_tf32_n16_kernel(
    const float* __restrict__ A, const float* __restrict__ B,
    const float* __restrict__ bias, float* __restrict__ C,
    int M, int K)
{
    __shared__ float As[32][132];
    __shared__ float Bs[32][20];

    int tid = threadIdx.x;
    int lane = tid & 31, wid = tid >> 5;
    int g = lane >> 2, tig = lane & 3;
    int row0 = blockIdx.x * 128;

    float acc[2][4];
#pragma unroll
    for (int ni = 0; ni < 2; ni++)
#pragma unroll
        for (int q = 0; q < 4; q++) acc[ni][q] = 0.f;

    int ar = tid >> 1;
    int akc0 = (tid & 1) * 16;
    int bk = tid >> 3;
    int bn = (tid & 7) * 2;

    for (int k0 = 0; k0 < K; k0 += 32) {
        int gr = row0 + ar;
#pragma unroll
        for (int q = 0; q < 4; q++) {
            int kc = akc0 + q * 4;
            float4 v = make_float4(0.f, 0.f, 0.f, 0.f);
            if (gr < M) v = *reinterpret_cast<const float4*>(&A[(long)gr * K + k0 + kc]);
            As[kc + 0][ar] = __uint_as_float(f2tf32(v.x));
            As[kc + 1][ar] = __uint_as_float(f2tf32(v.y));
            As[kc + 2][ar] = __uint_as_float(f2tf32(v.z));
            As[kc + 3][ar] = __uint_as_float(f2tf32(v.w));
        }
        Bs[bk][bn]     = __uint_as_float(f2tf32(B[(long)(k0 + bk) * 16 + bn]));
        Bs[bk][bn + 1] = __uint_as_float(f2tf32(B[(long)(k0 + bk) * 16 + bn + 1]));
        __syncthreads();

#pragma unroll
        for (int ks = 0; ks < 32; ks += 8) {
            int mb = wid * 16 + g;
            unsigned a[4];
            a[0] = __float_as_uint(As[ks + tig][mb]);
            a[1] = __float_as_uint(As[ks + tig][mb + 8]);
            a[2] = __float_as_uint(As[ks + tig + 4][mb]);
            a[3] = __float_as_uint(As[ks + tig + 4][mb + 8]);
#pragma unroll
            for (int ni = 0; ni < 2; ni++) {
                unsigned b0 = __float_as_uint(Bs[ks + tig][ni * 8 + g]);
                unsigned b1 = __float_as_uint(Bs[ks + tig + 4][ni * 8 + g]);
                mma_tf32(acc[ni], a, b0, b1);
            }
        }
        __syncthreads();
    }

#pragma unroll
    for (int ni = 0; ni < 2; ni++) {
        int c0 = ni * 8 + 2 * tig;
#pragma unroll
        for (int half = 0; half < 2; half++) {
            int gr = row0 + wid * 16 + g + half * 8;
            if (gr >= M) continue;
            C[(long)gr * 16 + c0]     = acc[ni][half * 2 + 0] + bias[c0];
            C[(long)gr * 16 + c0 + 1] = acc[ni][half * 2 + 1] + bias[c0 + 1];
        }
    }
}

// ---------------- fused softmax + aggregation over node range [n0, n1) -------
// Messages gathered fp16 (uint2 per lane = half the L2 traffic); weights,
// accumulation, bias, output all fp32. 4-edge batching keeps MLP ~4.
__global__ void agg_kernel(const float* __restrict__ bias, float* __restrict__ dst,
                           int n0, int n1)
{
    int n = n0 + ((blockIdx.x * blockDim.x + threadIdx.x) >> 5);
    int lane = threadIdx.x & 31;
    if (n >= n1) return;
    int beg = g_off[n], end = g_off[n + 1];
    float ad0 = g_ad[n * 2 + 0], ad1 = g_ad[n * 2 + 1];
    int head1 = lane >= 16;     // lane covers cols 4*lane..4*lane+3

    float4 acc = make_float4(0.f, 0.f, 0.f, 0.f);
    float s0 = 0.f, s1 = 0.f;

    for (int base = beg; base < end; base += 32) {
        int cnt = min(32, end - base);
        int sl = 0; float ex0 = 0.f, ex1 = 0.f;
        if (lane < cnt) {
            sl = g_csr[base + lane];
            float2 a = *reinterpret_cast<const float2*>(&g_as[sl * 2]);
            float e0 = a.x + ad0; e0 = fmaxf(e0, 0.2f * e0);
            float e1 = a.y + ad1; e1 = fmaxf(e1, 0.2f * e1);
            ex0 = __expf(e0);
            ex1 = __expf(e1);
        }
        int t = 0;
        for (; t + 4 <= cnt; t += 4) {
            int   sA = __shfl_sync(0xffffffffu, sl, t + 0);
            int   sB = __shfl_sync(0xffffffffu, sl, t + 1);
            int   sC = __shfl_sync(0xffffffffu, sl, t + 2);
            int   sD = __shfl_sync(0xffffffffu, sl, t + 3);
            float wA0 = __shfl_sync(0xffffffffu, ex0, t + 0);
            float wB0 = __shfl_sync(0xffffffffu, ex0, t + 1);
            float wC0 = __shfl_sync(0xffffffffu, ex0, t + 2);
            float wD0 = __shfl_sync(0xffffffffu, ex0, t + 3);
            float wA1 = __shfl_sync(0xffffffffu, ex1, t + 0);
            float wB1 = __shfl_sync(0xffffffffu, ex1, t + 1);
            float wC1 = __shfl_sync(0xffffffffu, ex1, t + 2);
            float wD1 = __shfl_sync(0xffffffffu, ex1, t + 3);
            // 4 independent 8B gathers in flight
            uint2 uA = reinterpret_cast<const uint2*>(&g_hh[(long)sA * HF])[lane];
            uint2 uB = reinterpret_cast<const uint2*>(&g_hh[(long)sB * HF])[lane];
            uint2 uC = reinterpret_cast<const uint2*>(&g_hh[(long)sC * HF])[lane];
            uint2 uD = reinterpret_cast<const uint2*>(&g_hh[(long)sD * HF])[lane];
            s0 += wA0 + wB0 + wC0 + wD0;
            s1 += wA1 + wB1 + wC1 + wD1;
            float wA = head1 ? wA1 : wA0;
            float wB = head1 ? wB1 : wB0;
            float wC = head1 ? wC1 : wC0;
            float wD = head1 ? wD1 : wD0;
            float2 fA0 = __half22float2(*reinterpret_cast<__half2*>(&uA.x));
            float2 fA1 = __half22float2(*reinterpret_cast<__half2*>(&uA.y));
            float2 fB0 = __half22float2(*reinterpret_cast<__half2*>(&uB.x));
            float2 fB1 = __half22float2(*reinterpret_cast<__half2*>(&uB.y));
            float2 fC0 = __half22float2(*reinterpret_cast<__half2*>(&uC.x));
            float2 fC1 = __half22float2(*reinterpret_cast<__half2*>(&uC.y));
            float2 fD0 = __half22float2(*reinterpret_cast<__half2*>(&uD.x));
            float2 fD1 = __half22float2(*reinterpret_cast<__half2*>(&uD.y));
            acc.x = fmaf(fA0.x, wA, acc.x); acc.y = fmaf(fA0.y, wA, acc.y);
            acc.z = fmaf(fA1.x, wA, acc.z); acc.w = fmaf(fA1.y, wA, acc.w);
            acc.x = fmaf(fB0.x, wB, acc.x); acc.y = fmaf(fB0.y, wB, acc.y);
            acc.z = fmaf(fB1.x, wB, acc.z); acc.w = fmaf(fB1.y, wB, acc.w);
            acc.x = fmaf(fC0.x, wC, acc.x); acc.y = fmaf(fC0.y, wC, acc.y);
            acc.z = fmaf(fC1.x, wC, acc.z); acc.w = fmaf(fC1.y, wC, acc.w);
            acc.x = fmaf(fD0.x, wD, acc.x); acc.y = fmaf(fD0.y, wD, acc.y);
            acc.z = fmaf(fD1.x, wD, acc.z); acc.w = fmaf(fD1.y, wD, acc.w);
        }
        for (; t < cnt; t++) {
            int s    = __shfl_sync(0xffffffffu, sl, t);
            float w0 = __shfl_sync(0xffffffffu, ex0, t);
            float w1 = __shfl_sync(0xffffffffu, ex1, t);
            s0 += w0; s1 += w1;
            uint2 u = reinterpret_cast<const uint2*>(&g_hh[(long)s * HF])[lane];
            float2 f0 = __half22float2(*reinterpret_cast<__half2*>(&u.x));
            float2 f1 = __half22float2(*reinterpret_cast<__half2*>(&u.y));
            float w = head1 ? w1 : w0;
            acc.x = fmaf(f0.x, w, acc.x);
            acc.y = fmaf(f0.y, w, acc.y);
            acc.z = fmaf(f1.x, w, acc.z);
            acc.w = fmaf(f1.y, w, acc.w);
        }
    }
    float r = head1 ? (1.f / (s1 + 1e-16f)) : (1.f / (s0 + 1e-16f));
    float4 b = reinterpret_cast<const float4*>(bias)[lane];
    float4 o;
    o.x = fmaxf(fmaf(acc.x, r, b.x), 0.f);
    o.y = fmaxf(fmaf(acc.y, r, b.y), 0.f);
    o.z = fmaxf(fmaf(acc.z, r, b.z), 0.f);
    o.w = fmaxf(fmaf(acc.w, r, b.w), 0.f);
    reinterpret_cast<float4*>(&dst[(long)n * HF])[lane] = o;
}

// ---------------- launch ------------------------------------------------------
extern "C" void kernel_launch(void* const* d_in, const int* in_sizes, int n_in,
                              void* d_out, int out_size)
{
    const float* x      = (const float*)d_in[0];
    const int*   ei     = (const int*)  d_in[1];
    const float* W1     = (const float*)d_in[2];
    const float* a_src1 = (const float*)d_in[3];
    const float* a_dst1 = (const float*)d_in[4];
    const float* b1     = (const float*)d_in[5];
    const float* W2     = (const float*)d_in[6];
    const float* a_src2 = (const float*)d_in[7];
    const float* a_dst2 = (const float*)d_in[8];
    const float* b2     = (const float*)d_in[9];
    const float* lw1    = (const float*)d_in[10];
    const float* lb1    = (const float*)d_in[11];
    const float* lw2    = (const float*)d_in[12];
    const float* lb2    = (const float*)d_in[13];
    const float* lw3    = (const float*)d_in[14];
    const float* lb3    = (const float*)d_in[15];

    int E = in_sizes[1] / 2;

    float* out    = (float*)d_out;
    float* emb    = out;                       // [N, 128]
    float* logits = out + (long)NNODES * HF;   // [N, 16]

    float *p_h2, *p_z1, *p_z2;
    cudaGetSymbolAddress((void**)&p_h2, g_h2);
    cudaGetSymbolAddress((void**)&p_z1, g_z1);
    cudaGetSymbolAddress((void**)&p_z2, g_z2);

    // side streams + events, created once (no device memory involved)
    static cudaStream_t sCSR = nullptr, s2 = nullptr;
    static cudaEvent_t evFork = nullptr, evCSR = nullptr, evReady = nullptr,
                       evG2h1 = nullptr, evB = nullptr, evEnd = nullptr;
    if (!sCSR) {
        cudaStreamCreateWithFlags(&sCSR, cudaStreamNonBlocking);
        cudaStreamCreateWithFlags(&s2, cudaStreamNonBlocking);
        cudaEventCreateWithFlags(&evFork, cudaEventDisableTiming);
        cudaEventCreateWithFlags(&evCSR, cudaEventDisableTiming);
        cudaEventCreateWithFlags(&evReady, cudaEventDisableTiming);
        cudaEventCreateWithFlags(&evG2h1, cudaEventDisableTiming);
        cudaEventCreateWithFlags(&evB, cudaEventDisableTiming);
        cudaEventCreateWithFlags(&evEnd, cudaEventDisableTiming);
    }

    int edgeBlocks  = cdiv(E, 256);
    int nodeBlocks  = cdiv(NNODES, 256);
    int node4Blocks = cdiv(cdiv(NNODES, 4), 256);

    const int N1 = NHALF1, N2 = NHALF2;
    int aggBlkH1 = cdiv(N1, 8), aggBlkH2 = cdiv(N2, 8);

    // ---------------- fork: CSR build on side stream ----------------
    cudaEventRecord(evFork, 0);
    cudaStreamWaitEvent(sCSR, evFork, 0);
    csr_zero_kernel<<<node4Blocks, 256, 0, sCSR>>>();
    csr_count_kernel<<<edgeBlocks, 256, 0, sCSR>>>(ei, E);
    csr_scan1_kernel<<<SCAN_NBLK, 1024, 0, sCSR>>>();
    csr_scan_fix_kernel<<<nodeBlocks, 256, 0, sCSR>>>();
    csr_scatter_kernel<<<edgeBlocks, 256, 0, sCSR>>>(ei, E);
    cudaEventRecord(evCSR, sCSR);

    // ---------------- main: GAT layer-1 GEMM (+fp16 h + fused alpha) ---------
    {
        dim3 grid(1, cdiv(NNODES, 128));
        gemm_tf32_alpha_kernel<<<grid, 256>>>(x, W1, a_src1, a_dst1,
                                              0, NNODES, HF, FDIM);
    }
    cudaStreamWaitEvent(0, evCSR, 0);
    cudaEventRecord(evReady, 0);
    cudaStreamWaitEvent(s2, evReady, 0);

    // ---------------- two-stream pipeline: agg1 -> gemm2 per half ------------
    agg_kernel<<<aggBlkH1, 256>>>(b1, p_h2, 0, N1);
    {
        dim3 grid(1, cdiv(N1, 128));
        gemm_tf32_alpha_kernel<<<grid, 256>>>(p_h2, W2, a_src2, a_dst2,
                                              0, N1, HF, HF);
    }
    cudaEventRecord(evG2h1, 0);
    agg_kernel<<<aggBlkH2, 256, 0, s2>>>(b1, p_h2, N1, NNODES);
    {
        dim3 grid(1, cdiv(N2, 128));
        gemm_tf32_alpha_kernel<<<grid, 256, 0, s2>>>(p_h2 + (long)N1 * HF, W2,
                                                     a_src2, a_dst2,
                                                     N1, N2, HF, HF);
    }
    cudaEventRecord(evB, s2);

    // cross-join: agg2 on either half needs BOTH gemm2 halves
    cudaStreamWaitEvent(0, evB, 0);
    cudaStreamWaitEvent(s2, evG2h1, 0);

    // ---------------- independent tails per half ----------------
    // main: half 1
    agg_kernel<<<aggBlkH1, 256>>>(b2, emb, 0, N1);
    {
        dim3 grid(4, cdiv(N1, 128));
        gemm_tf32_kernel<<<grid, 256>>>(emb, lw1, lb1, p_z1, N1, 512, HF, 1);
    }
    {
        dim3 grid(2, cdiv(N1, 128));
        gemm_tf32_kernel<<<grid, 256>>>(p_z1, lw2, lb2, p_z2, N1, 256, 512, 1);
    }
    gemm_tf32_n16_kernel<<<cdiv(N1, 128), 256>>>(p_z2, lw3, lb3, logits, N1, 256);

    // s2: half 2
    agg_kernel<<<aggBlkH2, 256, 0, s2>>>(b2, emb, N1, NNODES);
    {
        dim3 grid(4, cdiv(N2, 128));
        gemm_tf32_kernel<<<grid, 256, 0, s2>>>(emb + (long)N1 * HF, lw1, lb1,
                                               p_z1 + (long)N1 * 512, N2, 512, HF, 1);
    }
    {
        dim3 grid(2, cdiv(N2, 128));
        gemm_tf32_kernel<<<grid, 256, 0, s2>>>(p_z1 + (long)N1 * 512, lw2, lb2,
                                               p_z2 + (long)N1 * 256, N2, 256, 512, 1);
    }
    gemm_tf32_n16_kernel<<<cdiv(N2, 128), 256, 0, s2>>>(p_z2 + (long)N1 * 256, lw3, lb3,
                                                        logits + (long)N1 * 16, N2, 256);
    cudaEventRecord(evEnd, s2);
    cudaStreamWaitEvent(0, evEnd, 0);
}